// round 1
// baseline (speedup 1.0000x reference)
#include <cuda_runtime.h>
#include <cstddef>

// ---------------------------------------------------------------------------
// Sparse 3D UNet forward. All neighbor tables precomputed host-side (inputs).
// Each conv: out[i,:] = sum_k (feat[nbr[i,k],:] or 0) @ W[k]  -> *scale+bias
//            -> (+residual) -> relu -> (+pair-reduce of cat)
// ---------------------------------------------------------------------------

#define NMAX (1 << 20)   // max rows per level (N1 <= 81920; N2..N4 sized safe)

// Static device scratch (allocation is forbidden; __device__ globals are the
// sanctioned workaround).
__device__ float g_x1 [(size_t)NMAX * 32];
__device__ float g_x2 [(size_t)NMAX * 32];
__device__ float g_x3 [(size_t)NMAX * 64];
__device__ float g_x4 [(size_t)NMAX * 64];
__device__ float g_a  [(size_t)NMAX * 64];
__device__ float g_b  [(size_t)NMAX * 64];
__device__ float g_t  [(size_t)NMAX * 64];
__device__ float g_cat[(size_t)NMAX * 128];

// ---------------------------------------------------------------------------
// conv kernel: block = (8, BY) threads. Each thread: 1 row x (COUT/8) outputs.
// Per k: stage W[k] (CIN*COUT floats) + BY gathered input rows in smem.
// ---------------------------------------------------------------------------
template <int CIN, int COUT, int BY>
__global__ void __launch_bounds__(8 * BY)
conv_kernel(const float* __restrict__ in,       // [n_in, CIN]
            const int*   __restrict__ nbr,      // [n_out, 27]
            int n_out,
            const float* __restrict__ W,        // [27, CIN, COUT]
            const float* __restrict__ sb,       // scale[COUT], bias[COUT]
            const float* __restrict__ res_pre,  // nullable [n_out, COUT]
            const float* __restrict__ red_post, // nullable [n_out, 2*COUT]
            float* __restrict__ out)            // [n_out, COUT]
{
    constexpr int BX   = 8;
    constexpr int VEC  = COUT / BX;   // 4 (COUT=32) or 8 (COUT=64)
    constexpr int NT   = BX * BY;
    constexpr int ISTR = CIN + 1;     // pad to avoid bank conflicts

    __shared__ float w_s[CIN * COUT];
    __shared__ float in_s[BY * ISTR];

    const int tx   = threadIdx.x;
    const int ty   = threadIdx.y;
    const int tid  = ty * BX + tx;
    const int row0 = blockIdx.x * BY;
    const int row  = row0 + ty;

    float acc[VEC];
#pragma unroll
    for (int j = 0; j < VEC; j++) acc[j] = 0.f;

    for (int k = 0; k < 27; k++) {
        __syncthreads();  // previous iteration done reading smem
        // stage W[k] into smem (contiguous float4 copies)
        {
            const float4* Wk  = reinterpret_cast<const float4*>(W + (size_t)k * CIN * COUT);
            float4*       ws4 = reinterpret_cast<float4*>(w_s);
#pragma unroll
            for (int i = tid; i < CIN * COUT / 4; i += NT) ws4[i] = Wk[i];
        }
        // gather BY rows (masked: nbr == -1 or row out of range -> zeros)
        for (int i = tid; i < BY * CIN; i += NT) {
            int r  = i / CIN;
            int c  = i - r * CIN;
            int gr = row0 + r;
            float v = 0.f;
            if (gr < n_out) {
                int g = __ldg(nbr + (size_t)gr * 27 + k);
                if (g >= 0) v = __ldg(in + (size_t)g * CIN + c);
            }
            in_s[r * ISTR + c] = v;
        }
        __syncthreads();
        // accumulate
#pragma unroll 4
        for (int c = 0; c < CIN; c++) {
            float a = in_s[ty * ISTR + c];
#pragma unroll
            for (int j = 0; j < VEC / 4; j++) {
                float4 w = *reinterpret_cast<const float4*>(w_s + c * COUT + tx * VEC + j * 4);
                acc[j * 4 + 0] += a * w.x;
                acc[j * 4 + 1] += a * w.y;
                acc[j * 4 + 2] += a * w.z;
                acc[j * 4 + 3] += a * w.w;
            }
        }
    }

    if (row < n_out) {
#pragma unroll
        for (int j = 0; j < VEC / 4; j++) {
            const int co = tx * VEC + j * 4;
            float4 sc = *reinterpret_cast<const float4*>(sb + co);
            float4 bi = *reinterpret_cast<const float4*>(sb + COUT + co);
            float v0 = acc[j * 4 + 0] * sc.x + bi.x;
            float v1 = acc[j * 4 + 1] * sc.y + bi.y;
            float v2 = acc[j * 4 + 2] * sc.z + bi.z;
            float v3 = acc[j * 4 + 3] * sc.w + bi.w;
            if (res_pre) {
                float4 rp = *reinterpret_cast<const float4*>(res_pre + (size_t)row * COUT + co);
                v0 += rp.x; v1 += rp.y; v2 += rp.z; v3 += rp.w;
            }
            v0 = fmaxf(v0, 0.f);
            v1 = fmaxf(v1, 0.f);
            v2 = fmaxf(v2, 0.f);
            v3 = fmaxf(v3, 0.f);
            if (red_post) {
                const float* rp = red_post + (size_t)row * 2 * COUT + 2 * co;
                v0 += rp[0] + rp[1];
                v1 += rp[2] + rp[3];
                v2 += rp[4] + rp[5];
                v3 += rp[6] + rp[7];
            }
            float4 o; o.x = v0; o.y = v1; o.z = v2; o.w = v3;
            *reinterpret_cast<float4*>(out + (size_t)row * COUT + co) = o;
        }
    }
}

// concat along channels: out[r, 0:C] = a[r], out[r, C:2C] = b[r]   (C % 4 == 0)
__global__ void concat_kernel(const float* __restrict__ a, const float* __restrict__ b,
                              int n, int C4, float* __restrict__ out)
{
    int i = blockIdx.x * blockDim.x + threadIdx.x;
    int total = n * C4;
    if (i >= total) return;
    int r = i / C4, c = i - r * C4;
    const float4* a4 = reinterpret_cast<const float4*>(a);
    const float4* b4 = reinterpret_cast<const float4*>(b);
    float4*       o4 = reinterpret_cast<float4*>(out);
    o4[(size_t)r * 2 * C4 + c]      = a4[i];
    o4[(size_t)r * 2 * C4 + C4 + c] = b4[i];
}

// ---------------------------------------------------------------------------
// Host-side launchers
// ---------------------------------------------------------------------------
template <int CIN, int COUT, int BY>
static inline void conv(const float* in, const int* nbr, int n,
                        const float* W, const float* sb,
                        const float* res, const float* red, float* out)
{
    if (n <= 0) return;
    dim3 blk(8, BY);
    conv_kernel<CIN, COUT, BY><<<(n + BY - 1) / BY, blk>>>(in, nbr, n, W, sb, res, red, out);
}

static inline void concat(const float* a, const float* b, int n, int C, float* out)
{
    if (n <= 0) return;
    int total = n * (C / 4);
    concat_kernel<<<(total + 255) / 256, 256>>>(a, b, n, C / 4, out);
}

extern "C" void kernel_launch(void* const* d_in, const int* in_sizes, int n_in,
                              void* d_out, int out_size)
{
    (void)n_in; (void)out_size;
    const float* vf     = (const float*)d_in[0];
    const float* Win    = (const float*)d_in[1];
    const float* W32    = (const float*)d_in[2];
    const float* W64    = (const float*)d_in[3];
    const float* Wd3    = (const float*)d_in[4];
    const float* W6432  = (const float*)d_in[5];
    const float* W12864 = (const float*)d_in[6];
    const float* bn32   = (const float*)d_in[7];
    const float* bn64   = (const float*)d_in[8];
    const int* nbr1  = (const int*)d_in[9];
    const int* nbr2  = (const int*)d_in[10];
    const int* nbr3  = (const int*)d_in[11];
    const int* nbr4  = (const int*)d_in[12];
    const int* nbrd2 = (const int*)d_in[13];
    const int* nbrd3 = (const int*)d_in[14];
    const int* nbrd4 = (const int*)d_in[15];
    const int* nbri4 = (const int*)d_in[16];
    const int* nbri3 = (const int*)d_in[17];
    const int* nbri2 = (const int*)d_in[18];

    const int N1 = in_sizes[0] / 4;
    const int N2 = in_sizes[10] / 27;
    const int N3 = in_sizes[11] / 27;
    const int N4 = in_sizes[12] / 27;

    float *X1, *X2, *X3, *X4, *A, *B, *T, *CAT;
    cudaGetSymbolAddress((void**)&X1,  g_x1);
    cudaGetSymbolAddress((void**)&X2,  g_x2);
    cudaGetSymbolAddress((void**)&X3,  g_x3);
    cudaGetSymbolAddress((void**)&X4,  g_x4);
    cudaGetSymbolAddress((void**)&A,   g_a);
    cudaGetSymbolAddress((void**)&B,   g_b);
    cudaGetSymbolAddress((void**)&T,   g_t);
    cudaGetSymbolAddress((void**)&CAT, g_cat);
    float* OUT = (float*)d_out;

    // weight/bn offset helpers (floats)
    const int S32   = 27 * 32 * 32;    // W32 slice
    const int S64   = 27 * 64 * 64;    // W64 slice
    const int S6432 = 27 * 64 * 32;    // W6432 slice
    const int S1286 = 27 * 128 * 64;   // W12864 slice
#define BN32(i) (bn32 + (i) * 64)
#define BN64(i) (bn64 + (i) * 128)

    // ---- encoder ----
    conv<4,  32, 32>(vf, nbr1,  N1, Win,            BN32(0), 0, 0, A);   // A1
    conv<32, 32, 32>(A,  nbr1,  N1, W32 + 0 * S32,  BN32(1), 0, 0, X1);  // x1
    conv<32, 32, 32>(X1, nbrd2, N2, W32 + 1 * S32,  BN32(2), 0, 0, A);
    conv<32, 32, 32>(A,  nbr2,  N2, W32 + 2 * S32,  BN32(3), 0, 0, B);
    conv<32, 32, 32>(B,  nbr2,  N2, W32 + 3 * S32,  BN32(4), 0, 0, X2);  // x2
    conv<32, 64, 32>(X2, nbrd3, N3, Wd3,            BN64(0), 0, 0, A);
    conv<64, 64, 32>(A,  nbr3,  N3, W64 + 0 * S64,  BN64(1), 0, 0, B);
    conv<64, 64, 32>(B,  nbr3,  N3, W64 + 1 * S64,  BN64(2), 0, 0, X3);  // x3
    conv<64, 64, 32>(X3, nbrd4, N4, W64 + 2 * S64,  BN64(3), 0, 0, A);
    conv<64, 64, 32>(A,  nbr4,  N4, W64 + 3 * S64,  BN64(4), 0, 0, B);
    conv<64, 64, 32>(B,  nbr4,  N4, W64 + 4 * S64,  BN64(5), 0, 0, X4);  // x4

    // ---- level 4: basic block + concat-conv + reduce ----
    conv<64, 64, 32>(X4, nbr4, N4, W64 + 5 * S64, BN64(6), 0, 0, A);
    conv<64, 64, 32>(A,  nbr4, N4, W64 + 6 * S64, BN64(7), X4, 0, T);    // t
    concat(X4, T, N4, 64, CAT);                                          // [N4,128]
    conv<128, 64, 16>(CAT, nbr4, N4, W12864 + 0 * S1286, BN64(11), 0, CAT, A);  // U4

    // ---- up to level 3 ----
    conv<64, 64, 32>(A,  nbri4, N3, W64 + 7 * S64, BN64(8), 0, 0, B);    // xu4
    conv<64, 64, 32>(X3, nbr3,  N3, W64 + 8 * S64, BN64(9), 0, 0, A);
    conv<64, 64, 32>(A,  nbr3,  N3, W64 + 9 * S64, BN64(10), X3, 0, T);  // t3
    concat(B, T, N3, 64, CAT);
    conv<128, 64, 16>(CAT, nbr3, N3, W12864 + 1 * S1286, BN64(12), 0, CAT, A);  // U3

    // ---- up to level 2 ----
    conv<64, 32, 32>(A,  nbri3, N2, W6432 + 0 * S6432, BN32(11), 0, 0, B);  // xu3
    conv<32, 32, 32>(X2, nbr2,  N2, W32 + 4 * S32, BN32(5), 0, 0, A);
    conv<32, 32, 32>(A,  nbr2,  N2, W32 + 5 * S32, BN32(6), X2, 0, T);   // t2
    concat(B, T, N2, 32, CAT);                                           // [N2,64]
    conv<64, 32, 32>(CAT, nbr2, N2, W6432 + 1 * S6432, BN32(12), 0, CAT, A);  // U2

    // ---- up to level 1 ----
    conv<32, 32, 32>(A,  nbri2, N1, W32 + 6 * S32, BN32(7), 0, 0, B);    // xu2
    conv<32, 32, 32>(X1, nbr1,  N1, W32 + 7 * S32, BN32(8), 0, 0, A);
    conv<32, 32, 32>(A,  nbr1,  N1, W32 + 8 * S32, BN32(9), X1, 0, T);   // t1
    concat(B, T, N1, 32, CAT);                                           // [N1,64]
    conv<64, 32, 32>(CAT, nbr1, N1, W6432 + 2 * S6432, BN32(13), 0, CAT, A);  // U1

    // ---- head ----
    conv<32, 32, 32>(A, nbr1, N1, W32 + 9 * S32, BN32(10), 0, 0, OUT);

#undef BN32
#undef BN64
}

// round 2
// speedup vs baseline: 2.0238x; 2.0238x over previous
#include <cuda_runtime.h>
#include <cstddef>

// ---------------------------------------------------------------------------
// Sparse 3D UNet forward. All neighbor tables precomputed host-side (inputs).
// Each conv: out[i,:] = sum_k (feat[nbr[i,k],:] or 0) @ W[k]  -> *scale+bias
//            -> (+residual) -> relu -> (+pair-reduce of cat)
//
// R2: register row-blocking (ROWPT rows x VEC couts per thread) to cut LDS
// instructions per FMA ~3x; float4 gather staging; CIN chunking (<=64).
// ---------------------------------------------------------------------------

#define NMAX (1 << 20)

__device__ float g_x1 [(size_t)NMAX * 32];
__device__ float g_x2 [(size_t)NMAX * 32];
__device__ float g_x3 [(size_t)NMAX * 64];
__device__ float g_x4 [(size_t)NMAX * 64];
__device__ float g_a  [(size_t)NMAX * 64];
__device__ float g_b  [(size_t)NMAX * 64];
__device__ float g_t  [(size_t)NMAX * 64];
__device__ float g_cat[(size_t)NMAX * 128];

// ---------------------------------------------------------------------------
// conv kernel: block = (8, BY/ROWPT) threads.
// Each thread: ROWPT rows x (COUT/8) output channels.
// Per k (and CIN-chunk): stage W chunk + BY gathered rows into smem.
// ---------------------------------------------------------------------------
template <int CIN, int COUT, int BY, int ROWPT>
__global__ void __launch_bounds__(8 * BY / ROWPT)
conv_kernel(const float* __restrict__ in,       // [n_in, CIN]
            const int*   __restrict__ nbr,      // [n_out, 27]
            int n_out,
            const float* __restrict__ W,        // [27, CIN, COUT]
            const float* __restrict__ sb,       // scale[COUT], bias[COUT]
            const float* __restrict__ res_pre,  // nullable [n_out, COUT]
            const float* __restrict__ red_post, // nullable [n_out, 2*COUT]
            float* __restrict__ out)            // [n_out, COUT]
{
    constexpr int BX   = 8;
    constexpr int VEC  = COUT / BX;               // 4 or 8
    constexpr int NT   = BX * (BY / ROWPT);
    constexpr int CCH  = (CIN <= 64) ? CIN : 64;  // CIN chunk
    constexpr int ISTR = CCH + 4;                 // float4-aligned pad
    constexpr int C4   = CCH / 4;

    __shared__ float w_s[CCH * COUT];
    __shared__ float in_s[BY * ISTR];

    const int tx   = threadIdx.x;                 // 0..7  (cout groups)
    const int ty   = threadIdx.y;                 // 0..BY/ROWPT-1 (row groups)
    const int tid  = ty * BX + tx;
    const int row0 = blockIdx.x * BY;

    float acc[ROWPT][VEC];
#pragma unroll
    for (int i = 0; i < ROWPT; i++)
#pragma unroll
        for (int j = 0; j < VEC; j++) acc[i][j] = 0.f;

    for (int k = 0; k < 27; k++) {
#pragma unroll
        for (int cc = 0; cc < CIN; cc += CCH) {
            __syncthreads();
            // stage W[k] chunk [cc:cc+CCH, :] contiguously (float4)
            {
                const float4* Wk  = reinterpret_cast<const float4*>(
                    W + ((size_t)k * CIN + cc) * COUT);
                float4* ws4 = reinterpret_cast<float4*>(w_s);
#pragma unroll
                for (int i = tid; i < CCH * COUT / 4; i += NT) ws4[i] = Wk[i];
            }
            // gather BY rows, columns [cc, cc+CCH), float4 at a time
            for (int i = tid; i < BY * C4; i += NT) {
                int r  = i / C4;
                int c4 = i - r * C4;
                int gr = row0 + r;
                float4 v = make_float4(0.f, 0.f, 0.f, 0.f);
                if (gr < n_out) {
                    int g = __ldg(nbr + (size_t)gr * 27 + k);
                    if (g >= 0)
                        v = *reinterpret_cast<const float4*>(
                                in + (size_t)g * CIN + cc + c4 * 4);
                }
                *reinterpret_cast<float4*>(in_s + r * ISTR + c4 * 4) = v;
            }
            __syncthreads();
            // accumulate: ROWPT rows x VEC couts per thread
#pragma unroll 8
            for (int c = 0; c < CCH; c++) {
                float a[ROWPT];
#pragma unroll
                for (int i = 0; i < ROWPT; i++)
                    a[i] = in_s[(ty * ROWPT + i) * ISTR + c];
#pragma unroll
                for (int j = 0; j < VEC / 4; j++) {
                    float4 w = *reinterpret_cast<const float4*>(
                        w_s + c * COUT + tx * VEC + j * 4);
#pragma unroll
                    for (int i = 0; i < ROWPT; i++) {
                        acc[i][j * 4 + 0] += a[i] * w.x;
                        acc[i][j * 4 + 1] += a[i] * w.y;
                        acc[i][j * 4 + 2] += a[i] * w.z;
                        acc[i][j * 4 + 3] += a[i] * w.w;
                    }
                }
            }
        }
    }

#pragma unroll
    for (int i = 0; i < ROWPT; i++) {
        const int row = row0 + ty * ROWPT + i;
        if (row >= n_out) continue;
#pragma unroll
        for (int j = 0; j < VEC / 4; j++) {
            const int co = tx * VEC + j * 4;
            float4 sc = *reinterpret_cast<const float4*>(sb + co);
            float4 bi = *reinterpret_cast<const float4*>(sb + COUT + co);
            float v0 = acc[i][j * 4 + 0] * sc.x + bi.x;
            float v1 = acc[i][j * 4 + 1] * sc.y + bi.y;
            float v2 = acc[i][j * 4 + 2] * sc.z + bi.z;
            float v3 = acc[i][j * 4 + 3] * sc.w + bi.w;
            if (res_pre) {
                float4 rp = *reinterpret_cast<const float4*>(
                    res_pre + (size_t)row * COUT + co);
                v0 += rp.x; v1 += rp.y; v2 += rp.z; v3 += rp.w;
            }
            v0 = fmaxf(v0, 0.f);
            v1 = fmaxf(v1, 0.f);
            v2 = fmaxf(v2, 0.f);
            v3 = fmaxf(v3, 0.f);
            if (red_post) {
                const float* rp = red_post + (size_t)row * 2 * COUT + 2 * co;
                v0 += rp[0] + rp[1];
                v1 += rp[2] + rp[3];
                v2 += rp[4] + rp[5];
                v3 += rp[6] + rp[7];
            }
            float4 o; o.x = v0; o.y = v1; o.z = v2; o.w = v3;
            *reinterpret_cast<float4*>(out + (size_t)row * COUT + co) = o;
        }
    }
}

// concat along channels: out[r, 0:C] = a[r], out[r, C:2C] = b[r]   (C % 4 == 0)
__global__ void concat_kernel(const float* __restrict__ a, const float* __restrict__ b,
                              int n, int C4, float* __restrict__ out)
{
    int i = blockIdx.x * blockDim.x + threadIdx.x;
    int total = n * C4;
    if (i >= total) return;
    int r = i / C4, c = i - r * C4;
    const float4* a4 = reinterpret_cast<const float4*>(a);
    const float4* b4 = reinterpret_cast<const float4*>(b);
    float4*       o4 = reinterpret_cast<float4*>(out);
    o4[(size_t)r * 2 * C4 + c]      = a4[i];
    o4[(size_t)r * 2 * C4 + C4 + c] = b4[i];
}

// ---------------------------------------------------------------------------
template <int CIN, int COUT, int BY, int ROWPT>
static inline void conv(const float* in, const int* nbr, int n,
                        const float* W, const float* sb,
                        const float* res, const float* red, float* out)
{
    if (n <= 0) return;
    dim3 blk(8, BY / ROWPT);
    conv_kernel<CIN, COUT, BY, ROWPT><<<(n + BY - 1) / BY, blk>>>(
        in, nbr, n, W, sb, res, red, out);
}

static inline void concat(const float* a, const float* b, int n, int C, float* out)
{
    if (n <= 0) return;
    int total = n * (C / 4);
    concat_kernel<<<(total + 255) / 256, 256>>>(a, b, n, C / 4, out);
}

extern "C" void kernel_launch(void* const* d_in, const int* in_sizes, int n_in,
                              void* d_out, int out_size)
{
    (void)n_in; (void)out_size;
    const float* vf     = (const float*)d_in[0];
    const float* Win    = (const float*)d_in[1];
    const float* W32    = (const float*)d_in[2];
    const float* W64    = (const float*)d_in[3];
    const float* Wd3    = (const float*)d_in[4];
    const float* W6432  = (const float*)d_in[5];
    const float* W12864 = (const float*)d_in[6];
    const float* bn32   = (const float*)d_in[7];
    const float* bn64   = (const float*)d_in[8];
    const int* nbr1  = (const int*)d_in[9];
    const int* nbr2  = (const int*)d_in[10];
    const int* nbr3  = (const int*)d_in[11];
    const int* nbr4  = (const int*)d_in[12];
    const int* nbrd2 = (const int*)d_in[13];
    const int* nbrd3 = (const int*)d_in[14];
    const int* nbrd4 = (const int*)d_in[15];
    const int* nbri4 = (const int*)d_in[16];
    const int* nbri3 = (const int*)d_in[17];
    const int* nbri2 = (const int*)d_in[18];

    const int N1 = in_sizes[0] / 4;
    const int N2 = in_sizes[10] / 27;
    const int N3 = in_sizes[11] / 27;
    const int N4 = in_sizes[12] / 27;

    float *X1, *X2, *X3, *X4, *A, *B, *T, *CAT;
    cudaGetSymbolAddress((void**)&X1,  g_x1);
    cudaGetSymbolAddress((void**)&X2,  g_x2);
    cudaGetSymbolAddress((void**)&X3,  g_x3);
    cudaGetSymbolAddress((void**)&X4,  g_x4);
    cudaGetSymbolAddress((void**)&A,   g_a);
    cudaGetSymbolAddress((void**)&B,   g_b);
    cudaGetSymbolAddress((void**)&T,   g_t);
    cudaGetSymbolAddress((void**)&CAT, g_cat);
    float* OUT = (float*)d_out;

    const int S32   = 27 * 32 * 32;
    const int S64   = 27 * 64 * 64;
    const int S6432 = 27 * 64 * 32;
    const int S1286 = 27 * 128 * 64;
#define BN32(i) (bn32 + (i) * 64)
#define BN64(i) (bn64 + (i) * 128)

    // ---- encoder ----
    conv<4,  32, 128, 4>(vf, nbr1,  N1, Win,           BN32(0), 0, 0, A);
    conv<32, 32, 128, 4>(A,  nbr1,  N1, W32 + 0 * S32, BN32(1), 0, 0, X1);  // x1
    conv<32, 32, 128, 4>(X1, nbrd2, N2, W32 + 1 * S32, BN32(2), 0, 0, A);
    conv<32, 32, 128, 4>(A,  nbr2,  N2, W32 + 2 * S32, BN32(3), 0, 0, B);
    conv<32, 32, 128, 4>(B,  nbr2,  N2, W32 + 3 * S32, BN32(4), 0, 0, X2);  // x2
    conv<32, 64, 64, 2>(X2, nbrd3, N3, Wd3,           BN64(0), 0, 0, A);
    conv<64, 64, 64, 2>(A,  nbr3,  N3, W64 + 0 * S64, BN64(1), 0, 0, B);
    conv<64, 64, 64, 2>(B,  nbr3,  N3, W64 + 1 * S64, BN64(2), 0, 0, X3);   // x3
    conv<64, 64, 64, 2>(X3, nbrd4, N4, W64 + 2 * S64, BN64(3), 0, 0, A);
    conv<64, 64, 64, 2>(A,  nbr4,  N4, W64 + 3 * S64, BN64(4), 0, 0, B);
    conv<64, 64, 64, 2>(B,  nbr4,  N4, W64 + 4 * S64, BN64(5), 0, 0, X4);   // x4

    // ---- level 4 ----
    conv<64, 64, 64, 2>(X4, nbr4, N4, W64 + 5 * S64, BN64(6), 0, 0, A);
    conv<64, 64, 64, 2>(A,  nbr4, N4, W64 + 6 * S64, BN64(7), X4, 0, T);    // t
    concat(X4, T, N4, 64, CAT);
    conv<128, 64, 64, 2>(CAT, nbr4, N4, W12864 + 0 * S1286, BN64(11), 0, CAT, A);

    // ---- up to level 3 ----
    conv<64, 64, 64, 2>(A,  nbri4, N3, W64 + 7 * S64, BN64(8), 0, 0, B);    // xu4
    conv<64, 64, 64, 2>(X3, nbr3,  N3, W64 + 8 * S64, BN64(9), 0, 0, A);
    conv<64, 64, 64, 2>(A,  nbr3,  N3, W64 + 9 * S64, BN64(10), X3, 0, T);  // t3
    concat(B, T, N3, 64, CAT);
    conv<128, 64, 64, 2>(CAT, nbr3, N3, W12864 + 1 * S1286, BN64(12), 0, CAT, A);

    // ---- up to level 2 ----
    conv<64, 32, 128, 4>(A,  nbri3, N2, W6432 + 0 * S6432, BN32(11), 0, 0, B);  // xu3
    conv<32, 32, 128, 4>(X2, nbr2,  N2, W32 + 4 * S32, BN32(5), 0, 0, A);
    conv<32, 32, 128, 4>(A,  nbr2,  N2, W32 + 5 * S32, BN32(6), X2, 0, T);  // t2
    concat(B, T, N2, 32, CAT);
    conv<64, 32, 128, 4>(CAT, nbr2, N2, W6432 + 1 * S6432, BN32(12), 0, CAT, A);

    // ---- up to level 1 ----
    conv<32, 32, 128, 4>(A,  nbri2, N1, W32 + 6 * S32, BN32(7), 0, 0, B);   // xu2
    conv<32, 32, 128, 4>(X1, nbr1,  N1, W32 + 7 * S32, BN32(8), 0, 0, A);
    conv<32, 32, 128, 4>(A,  nbr1,  N1, W32 + 8 * S32, BN32(9), X1, 0, T);  // t1
    concat(B, T, N1, 32, CAT);
    conv<64, 32, 128, 4>(CAT, nbr1, N1, W6432 + 2 * S6432, BN32(13), 0, CAT, A);

    // ---- head ----
    conv<32, 32, 128, 4>(A, nbr1, N1, W32 + 9 * S32, BN32(10), 0, 0, OUT);

#undef BN32
#undef BN64
}